// round 16
// baseline (speedup 1.0000x reference)
#include <cuda_runtime.h>
#include <cuda_fp16.h>
#include <cstdint>

#define T_LEN 32768
#define DM 512
#define DH 512
#define LCH 32
#define NCH (T_LEN / LCH)
#define NSUP 32
#define CPS (NCH / NSUP)

#define STAGES 3
#define BKH 32
#define STAGE_BYTES 24576          // A 8KB + B 16KB
#define SMEM_DYN (STAGES * STAGE_BYTES)   // 72 KB

// ---------------- device scratch ----------------
__device__ __half g_Buh_re[(size_t)T_LEN * DH];
__device__ __half g_Buh_im[(size_t)T_LEN * DH];
__device__ __half g_xh[(size_t)T_LEN * DM];
__device__ __half g_xsh_re[(size_t)T_LEN * DH];
__device__ __half g_xsh_im[(size_t)T_LEN * DH];
__device__ __half g_Bh[2][DH * DM];
__device__ __half g_Ch[2][DM * DH];     // Ch[1] = -C_im
__device__ float g_lam_re[DH], g_lam_im[DH], g_gam[DH];
__device__ float g_lamL_re[DH], g_lamL_im[DH];
__device__ float g_lamS_re[DH], g_lamS_im[DH];
__device__ float g_cb_re[NCH * DH], g_cb_im[NCH * DH];
__device__ float g_init_re[NCH * DH], g_init_im[NCH * DH];
__device__ float g_sb_re[NSUP * DH], g_sb_im[NSUP * DH];
__device__ float g_sinit_re[NSUP * DH], g_sinit_im[NSUP * DH];
__device__ float g_fin_re[DH], g_fin_im[DH];
__device__ int   g_anystart[NCH];
__device__ int   g_sany[NSUP];
__device__ unsigned char g_start[T_LEN];

// ---------------- start-flag normalization ----------------
__global__ void start_convert_kernel(const unsigned int* __restrict__ raw) {
    __shared__ int s_isu8;
    int tid = threadIdx.x;
    if (tid == 0) s_isu8 = 0;
    __syncthreads();
    for (int i = tid; i < T_LEN / 4; i += blockDim.x)
        if (raw[i] > 1u) s_isu8 = 1;
    __syncthreads();
    if (s_isu8) {
        const unsigned char* b = (const unsigned char*)raw;
        for (int t = tid; t < T_LEN; t += blockDim.x) g_start[t] = b[t] ? 1 : 0;
    } else {
        for (int t = tid; t < T_LEN; t += blockDim.x) g_start[t] = raw[t] ? 1 : 0;
    }
}

// ---------------- prep ----------------
__global__ void prep_kernel(const float* __restrict__ theta_log,
                            const float* __restrict__ nu_log,
                            const float* __restrict__ gamma_log) {
    int h = threadIdx.x;
    float nu = expf(nu_log[h]);
    float th = expf(theta_log[h]);
    float mag = expf(-nu);
    float lr = mag * cosf(th);
    float li = mag * sinf(th);
    g_lam_re[h] = lr; g_lam_im[h] = li;
    g_gam[h] = expf(gamma_log[h]);
    float ar = 1.f, ai = 0.f;
#pragma unroll
    for (int i = 0; i < LCH; i++) {
        float nr = ar * lr - ai * li, ni = ar * li + ai * lr;
        ar = nr; ai = ni;
    }
    g_lamL_re[h] = ar; g_lamL_im[h] = ai;
    float sr = 1.f, si = 0.f;
#pragma unroll
    for (int i = 0; i < CPS; i++) {
        float nr = sr * ar - si * ai, ni = sr * ai + si * ar;
        sr = nr; si = ni;
    }
    g_lamS_re[h] = sr; g_lamS_im[h] = si;
}

// ---------------- operand conversion ----------------
__global__ void convert_x_kernel(const float* __restrict__ x) {
    size_t i = (size_t)(blockIdx.x * blockDim.x + threadIdx.x) * 4;
    float4 v = *(const float4*)(x + i);
    *(__half2*)(g_xh + i)     = __floats2half2_rn(v.x, v.y);
    *(__half2*)(g_xh + i + 2) = __floats2half2_rn(v.z, v.w);
}

__global__ void convert_params_kernel(const float* __restrict__ B_re,
                                      const float* __restrict__ B_im,
                                      const float* __restrict__ C_re,
                                      const float* __restrict__ C_im) {
    int i = blockIdx.x * blockDim.x + threadIdx.x;
    g_Bh[0][i] = __float2half(B_re[i]);
    g_Bh[1][i] = __float2half(B_im[i]);
    g_Ch[0][i] = __float2half(C_re[i]);
    g_Ch[1][i] = __float2half(-C_im[i]);
}

// ---------------- asm helpers ----------------
__device__ __forceinline__ uint32_t smem_u32(const void* p) {
    uint32_t a;
    asm("{ .reg .u64 t; cvta.to.shared.u64 t, %1; cvt.u32.u64 %0, t; }" : "=r"(a) : "l"(p));
    return a;
}
__device__ __forceinline__ void cp16(uint32_t dst, const void* src) {
    asm volatile("cp.async.cg.shared.global [%0], [%1], 16;" :: "r"(dst), "l"(src));
}
#define CP_COMMIT() asm volatile("cp.async.commit_group;" ::: "memory")
#define CP_WAIT1()  asm volatile("cp.async.wait_group 1;" ::: "memory")
#define LDM_X4(r, a)                                                     \
    asm volatile("ldmatrix.sync.aligned.m8n8.x4.shared.b16 {%0,%1,%2,%3}, [%4];" \
        : "=r"((r)[0]), "=r"((r)[1]), "=r"((r)[2]), "=r"((r)[3]) : "r"(a))

__device__ __forceinline__ void mma_f16(float& c0, float& c1, float& c2, float& c3,
                                        uint32_t a0, uint32_t a1, uint32_t a2, uint32_t a3,
                                        uint32_t b0, uint32_t b1) {
    asm volatile(
        "mma.sync.aligned.m16n8k16.row.col.f32.f16.f16.f32 "
        "{%0,%1,%2,%3}, {%4,%5,%6,%7}, {%8,%9}, {%0,%1,%2,%3};"
        : "+f"(c0), "+f"(c1), "+f"(c2), "+f"(c3)
        : "r"(a0), "r"(a1), "r"(a2), "r"(a3), "r"(b0), "r"(b1));
}

// ---------------- pipelined fp16 GEMM, tile 128x256 ----------------
// mode 0: Bu planes. A = g_xh; B = g_Bh[z]. K=512. epi *gam -> half Bu planes.
// mode 2: outputs.   A = xsh_re|xsh_im; B = Ch0|Ch1. K=1024. epi + x*D (fp32 out).
// 8 warps (2m x 4n), warp tile 64x64, BK=32, 3-stage cp.async, ldmatrix.
__global__ __launch_bounds__(256, 1) void gemm_f16p_kernel(
    const float* __restrict__ x, const float* __restrict__ Dvec,
    float* __restrict__ Cout_ext, int mode)
{
    extern __shared__ __align__(16) char dsm[];
    const uint32_t smb = smem_u32(dsm);

    const int t    = threadIdx.x;
    const int lane = t & 31;
    const int wid  = t >> 5;
    const int wm0  = (wid >> 2) * 64;
    const int wn0  = (wid & 3) * 64;
    const int m0   = blockIdx.y * 128;
    const int n0   = blockIdx.x * 256;

    int KT = (mode == 0) ? DM / BKH : 2 * DH / BKH;

    float acc[4][8][4];
#pragma unroll
    for (int a = 0; a < 4; a++)
#pragma unroll
        for (int b = 0; b < 8; b++)
#pragma unroll
            for (int c = 0; c < 4; c++) acc[a][b][c] = 0.f;

    // cp.async chunk coords: i 0..1 -> A (512 chunks), i 2..5 -> B (1024 chunks)
    int cl[6], cs[6], cr[6], ck[6];
#pragma unroll
    for (int i = 0; i < 6; i++) {
        int g = (i < 2) ? (t + i * 256) : (t + (i - 2) * 256);
        cl[i] = g >> 3;
        cs[i] = g & 7;
        cr[i] = (cl[i] << 1) + (cs[i] >> 2);
        ck[i] = (cs[i] & 3) * 8;
    }

#define ISSUE(s) do {                                                         \
        int kg = (s) * BKH;                                                   \
        const __half* Ap_; const __half* Bp_; int kb_;                        \
        if (mode == 0) { Ap_ = g_xh; Bp_ = g_Bh[blockIdx.z]; kb_ = kg; }      \
        else if (kg < DH) { Ap_ = g_xsh_re; Bp_ = g_Ch[0]; kb_ = kg; }        \
        else              { Ap_ = g_xsh_im; Bp_ = g_Ch[1]; kb_ = kg - DH; }   \
        uint32_t st_ = smb + ((s) % STAGES) * STAGE_BYTES;                    \
        _Pragma("unroll")                                                     \
        for (int i = 0; i < 2; i++) {                                         \
            uint32_t off = cl[i] * 128 + ((cs[i] ^ (cl[i] & 7)) << 4);        \
            cp16(st_ + off, Ap_ + (size_t)(m0 + cr[i]) * DM + kb_ + ck[i]);   \
        }                                                                     \
        _Pragma("unroll")                                                     \
        for (int i = 2; i < 6; i++) {                                         \
            uint32_t off = cl[i] * 128 + ((cs[i] ^ (cl[i] & 7)) << 4);        \
            cp16(st_ + 8192 + off, Bp_ + (size_t)(n0 + cr[i]) * DM + kb_ + ck[i]); \
        }                                                                     \
    } while (0)

#pragma unroll
    for (int s = 0; s < STAGES - 1; s++) { ISSUE(s); CP_COMMIT(); }

    for (int kt = 0; kt < KT; kt++) {
        CP_WAIT1();
        __syncthreads();
        if (kt + STAGES - 1 < KT) ISSUE(kt + STAGES - 1);
        CP_COMMIT();

        uint32_t Ast = smb + (kt % STAGES) * STAGE_BYTES;
        uint32_t Bst = Ast + 8192;

#pragma unroll
        for (int j = 0; j < 2; j++) {
            uint32_t af[4][4];
#pragma unroll
            for (int mt = 0; mt < 4; mt++) {
                int r  = wm0 + mt * 16 + (lane & 7) + ((lane >> 3) & 1) * 8;
                int kc = 2 * j + (lane >> 4);
                int line = r >> 1, sub = ((r & 1) << 2) | kc;
                LDM_X4(af[mt], Ast + line * 128 + ((sub ^ (line & 7)) << 4));
            }
            uint32_t bq[4][4];
#pragma unroll
            for (int np = 0; np < 4; np++) {
                int n  = wn0 + np * 16 + (lane & 7) + ((lane >> 4) ? 8 : 0);
                int kc = 2 * j + ((lane >> 3) & 1);
                int line = n >> 1, sub = ((n & 1) << 2) | kc;
                LDM_X4(bq[np], Bst + line * 128 + ((sub ^ (line & 7)) << 4));
            }
#pragma unroll
            for (int mt = 0; mt < 4; mt++)
#pragma unroll
                for (int nt = 0; nt < 8; nt++)
                    mma_f16(acc[mt][nt][0], acc[mt][nt][1], acc[mt][nt][2], acc[mt][nt][3],
                            af[mt][0], af[mt][1], af[mt][2], af[mt][3],
                            bq[nt >> 1][(nt & 1) * 2], bq[nt >> 1][(nt & 1) * 2 + 1]);
        }
    }

    // ---- epilogue ----
#pragma unroll
    for (int mt = 0; mt < 4; mt++) {
        int row0 = m0 + wm0 + mt * 16 + (lane >> 2);
#pragma unroll
        for (int nt = 0; nt < 8; nt++) {
            int col0 = n0 + wn0 + nt * 8 + (lane & 3) * 2;
            float v0 = acc[mt][nt][0], v1 = acc[mt][nt][1];
            float v2 = acc[mt][nt][2], v3 = acc[mt][nt][3];
            if (mode == 0) {
                __half* base = blockIdx.z ? g_Buh_im : g_Buh_re;
                float gx = g_gam[col0], gy = g_gam[col0 + 1];
                *(__half2*)&base[(size_t)row0 * DH + col0] =
                    __floats2half2_rn(v0 * gx, v1 * gy);
                *(__half2*)&base[(size_t)(row0 + 8) * DH + col0] =
                    __floats2half2_rn(v2 * gx, v3 * gy);
            } else {
                float2 dv = *(const float2*)&Dvec[col0];
                float2 x0 = *(const float2*)&x[(size_t)row0 * DM + col0];
                float2 x1 = *(const float2*)&x[(size_t)(row0 + 8) * DM + col0];
                *(float2*)&Cout_ext[(size_t)row0 * DM + col0] =
                    make_float2(v0 + x0.x * dv.x, v1 + x0.y * dv.y);
                *(float2*)&Cout_ext[(size_t)(row0 + 8) * DM + col0] =
                    make_float2(v2 + x1.x * dv.x, v3 + x1.y * dv.y);
            }
        }
    }
}

// ---------------- scan passes (2 h per thread, half2/float2) ----------------
__global__ void chunk_reduce_kernel() {
    int c = blockIdx.x, h2 = threadIdx.x;          // 256 threads, h = 2*h2
    int h = h2 * 2;
    float2 lr = *(const float2*)&g_lam_re[h];
    float2 li = *(const float2*)&g_lam_im[h];
    float sr0 = 0.f, si0 = 0.f, sr1 = 0.f, si1 = 0.f;
    int any = 0, base = c * LCH;
#pragma unroll 4
    for (int t = 0; t < LCH; t++) {
        int s = g_start[base + t];
        any |= s;
        __half2 brh = *(const __half2*)&g_Buh_re[(size_t)(base + t) * DH + h];
        __half2 bih = *(const __half2*)&g_Buh_im[(size_t)(base + t) * DH + h];
        float2 br = __half22float2(brh);
        float2 bi = __half22float2(bih);
        if (s) { sr0 = br.x; si0 = bi.x; sr1 = br.y; si1 = bi.y; }
        else {
            float n0 = lr.x * sr0 - li.x * si0 + br.x;
            float m0 = lr.x * si0 + li.x * sr0 + bi.x;
            float n1 = lr.y * sr1 - li.y * si1 + br.y;
            float m1 = lr.y * si1 + li.y * sr1 + bi.y;
            sr0 = n0; si0 = m0; sr1 = n1; si1 = m1;
        }
    }
    *(float2*)&g_cb_re[c * DH + h] = make_float2(sr0, sr1);
    *(float2*)&g_cb_im[c * DH + h] = make_float2(si0, si1);
    if (h2 == 0) g_anystart[c] = any;
}

__global__ void super_reduce_kernel() {
    int s = blockIdx.x, h = threadIdx.x;
    float Lr = g_lamL_re[h], Li = g_lamL_im[h];
    float sr = 0.f, si = 0.f;
    int anyS = 0, base = s * CPS;
#pragma unroll 4
    for (int j = 0; j < CPS; j++) {
        int c = base + j, a = g_anystart[c];
        anyS |= a;
        float br = g_cb_re[c * DH + h], bi = g_cb_im[c * DH + h];
        if (a) { sr = br; si = bi; }
        else {
            float nr = Lr * sr - Li * si + br, ni = Lr * si + Li * sr + bi;
            sr = nr; si = ni;
        }
    }
    g_sb_re[s * DH + h] = sr; g_sb_im[s * DH + h] = si;
    if (h == 0) g_sany[s] = anyS;
}

__global__ void super_scan_kernel(const float* __restrict__ state) {
    int h = threadIdx.x;
    float sr = state[h], si = 0.f;
    float Sr = g_lamS_re[h], Si = g_lamS_im[h];
#pragma unroll 4
    for (int s = 0; s < NSUP; s++) {
        g_sinit_re[s * DH + h] = sr; g_sinit_im[s * DH + h] = si;
        float br = g_sb_re[s * DH + h], bi = g_sb_im[s * DH + h];
        if (g_sany[s]) { sr = br; si = bi; }
        else {
            float nr = Sr * sr - Si * si + br, ni = Sr * si + Si * sr + bi;
            sr = nr; si = ni;
        }
    }
}

__global__ void super_expand_kernel() {
    int s = blockIdx.x, h = threadIdx.x;
    float Lr = g_lamL_re[h], Li = g_lamL_im[h];
    float sr = g_sinit_re[s * DH + h], si = g_sinit_im[s * DH + h];
    int base = s * CPS;
#pragma unroll 4
    for (int j = 0; j < CPS; j++) {
        int c = base + j;
        g_init_re[c * DH + h] = sr; g_init_im[c * DH + h] = si;
        float br = g_cb_re[c * DH + h], bi = g_cb_im[c * DH + h];
        if (g_anystart[c]) { sr = br; si = bi; }
        else {
            float nr = Lr * sr - Li * si + br, ni = Lr * si + Li * sr + bi;
            sr = nr; si = ni;
        }
    }
}

// expand: fp16 xs planes for GEMM2 + fp32 final-state capture (2 h / thread)
__global__ void chunk_expand_kernel() {
    int c = blockIdx.x, h2 = threadIdx.x;
    int h = h2 * 2;
    float2 lr = *(const float2*)&g_lam_re[h];
    float2 li = *(const float2*)&g_lam_im[h];
    float2 ir = *(const float2*)&g_init_re[c * DH + h];
    float2 ii = *(const float2*)&g_init_im[c * DH + h];
    float sr0 = ir.x, si0 = ii.x, sr1 = ir.y, si1 = ii.y;
    int base = c * LCH;
#pragma unroll 4
    for (int t = 0; t < LCH; t++) {
        __half2 brh = *(const __half2*)&g_Buh_re[(size_t)(base + t) * DH + h];
        __half2 bih = *(const __half2*)&g_Buh_im[(size_t)(base + t) * DH + h];
        float2 br = __half22float2(brh);
        float2 bi = __half22float2(bih);
        if (g_start[base + t]) { sr0 = br.x; si0 = bi.x; sr1 = br.y; si1 = bi.y; }
        else {
            float n0 = lr.x * sr0 - li.x * si0 + br.x;
            float m0 = lr.x * si0 + li.x * sr0 + bi.x;
            float n1 = lr.y * sr1 - li.y * si1 + br.y;
            float m1 = lr.y * si1 + li.y * sr1 + bi.y;
            sr0 = n0; si0 = m0; sr1 = n1; si1 = m1;
        }
        *(__half2*)&g_xsh_re[(size_t)(base + t) * DH + h] = __floats2half2_rn(sr0, sr1);
        *(__half2*)&g_xsh_im[(size_t)(base + t) * DH + h] = __floats2half2_rn(si0, si1);
    }
    if (c == NCH - 1) {
        *(float2*)&g_fin_re[h] = make_float2(sr0, sr1);
        *(float2*)&g_fin_im[h] = make_float2(si0, si1);
    }
}

__global__ void write_state_kernel(float* __restrict__ out, int mode) {
    int h = threadIdx.x;
    if (mode == 0) { out[h] = g_fin_re[h]; out[DH + h] = g_fin_im[h]; }
    else           { out[h] = g_fin_re[h]; }
}

// ---------------- launch ----------------
extern "C" void kernel_launch(void* const* d_in, const int* in_sizes, int n_in,
                              void* d_out, int out_size) {
    const float*        state     = (const float*)d_in[0];
    const float*        x         = (const float*)d_in[1];
    const unsigned int* start_raw = (const unsigned int*)d_in[2];
    const float*        theta_log = (const float*)d_in[3];
    const float*        nu_log    = (const float*)d_in[4];
    const float*        gamma_log = (const float*)d_in[5];
    const float*        B_re      = (const float*)d_in[6];
    const float*        B_im      = (const float*)d_in[7];
    const float*        C_re      = (const float*)d_in[8];
    const float*        C_im      = (const float*)d_in[9];
    const float*        Dvec      = (const float*)d_in[10];

    const long long full = (long long)T_LEN * DM;
    int state_elems = (int)((long long)out_size - full);
    int mode; int out_off;
    if (state_elems >= 2 * DH) { mode = 0; out_off = 2 * DH; }
    else                       { mode = 1; out_off = DH; }

    float* out = (float*)d_out;
    float* outputs = out + out_off;

    static int smem_set = 0;
    if (!smem_set) {
        cudaFuncSetAttribute(gemm_f16p_kernel,
                             cudaFuncAttributeMaxDynamicSharedMemorySize, SMEM_DYN);
        smem_set = 1;
    }

    start_convert_kernel<<<1, 256>>>(start_raw);
    prep_kernel<<<1, DH>>>(theta_log, nu_log, gamma_log);
    convert_x_kernel<<<(T_LEN * DM / 4) / 256, 256>>>(x);
    convert_params_kernel<<<(DH * DM) / 256, 256>>>(B_re, B_im, C_re, C_im);

    dim3 g1(DH / 256, T_LEN / 128, 2);
    gemm_f16p_kernel<<<g1, 256, SMEM_DYN>>>(x, Dvec, nullptr, 0);

    chunk_reduce_kernel<<<NCH, 256>>>();
    super_reduce_kernel<<<NSUP, DH>>>();
    super_scan_kernel<<<1, DH>>>(state);
    super_expand_kernel<<<NSUP, DH>>>();
    chunk_expand_kernel<<<NCH, 256>>>();

    dim3 g2(DM / 256, T_LEN / 128, 1);
    gemm_f16p_kernel<<<g2, 256, SMEM_DYN>>>(x, Dvec, outputs, 2);

    write_state_kernel<<<1, DH>>>(out, mode);
}

// round 17
// speedup vs baseline: 1.1134x; 1.1134x over previous
#include <cuda_runtime.h>
#include <cuda_fp16.h>
#include <cstdint>

#define T_LEN 32768
#define DM 512
#define DH 512
#define LCH 32
#define NCH (T_LEN / LCH)
#define NSUP 32
#define CPS (NCH / NSUP)

#define STAGES 5
#define BKH 32
#define STAGE_BYTES 16384          // A 8KB + B 8KB
#define SMEM_DYN (STAGES * STAGE_BYTES)   // 80 KB

// ---------------- device scratch ----------------
__device__ __half g_Buh_re[(size_t)T_LEN * DH];
__device__ __half g_Buh_im[(size_t)T_LEN * DH];
__device__ __half g_xh[(size_t)T_LEN * DM];
__device__ __half g_xsh_re[(size_t)T_LEN * DH];
__device__ __half g_xsh_im[(size_t)T_LEN * DH];
__device__ __half g_Bh[2][DH * DM];
__device__ __half g_Ch[2][DM * DH];     // Ch[1] = -C_im
__device__ float g_lam_re[DH], g_lam_im[DH], g_gam[DH];
__device__ float g_lamL_re[DH], g_lamL_im[DH];
__device__ float g_lamS_re[DH], g_lamS_im[DH];
__device__ float g_cb_re[NCH * DH], g_cb_im[NCH * DH];
__device__ float g_init_re[NCH * DH], g_init_im[NCH * DH];
__device__ float g_sb_re[NSUP * DH], g_sb_im[NSUP * DH];
__device__ float g_sinit_re[NSUP * DH], g_sinit_im[NSUP * DH];
__device__ float g_fin_re[DH], g_fin_im[DH];
__device__ int   g_anystart[NCH];
__device__ int   g_sany[NSUP];
__device__ unsigned char g_start[T_LEN];

// ---------------- start-flag normalization ----------------
__global__ void start_convert_kernel(const unsigned int* __restrict__ raw) {
    __shared__ int s_isu8;
    int tid = threadIdx.x;
    if (tid == 0) s_isu8 = 0;
    __syncthreads();
    for (int i = tid; i < T_LEN / 4; i += blockDim.x)
        if (raw[i] > 1u) s_isu8 = 1;
    __syncthreads();
    if (s_isu8) {
        const unsigned char* b = (const unsigned char*)raw;
        for (int t = tid; t < T_LEN; t += blockDim.x) g_start[t] = b[t] ? 1 : 0;
    } else {
        for (int t = tid; t < T_LEN; t += blockDim.x) g_start[t] = raw[t] ? 1 : 0;
    }
}

// ---------------- prep ----------------
__global__ void prep_kernel(const float* __restrict__ theta_log,
                            const float* __restrict__ nu_log,
                            const float* __restrict__ gamma_log) {
    int h = threadIdx.x;
    float nu = expf(nu_log[h]);
    float th = expf(theta_log[h]);
    float mag = expf(-nu);
    float lr = mag * cosf(th);
    float li = mag * sinf(th);
    g_lam_re[h] = lr; g_lam_im[h] = li;
    g_gam[h] = expf(gamma_log[h]);
    float ar = 1.f, ai = 0.f;
#pragma unroll
    for (int i = 0; i < LCH; i++) {
        float nr = ar * lr - ai * li, ni = ar * li + ai * lr;
        ar = nr; ai = ni;
    }
    g_lamL_re[h] = ar; g_lamL_im[h] = ai;
    float sr = 1.f, si = 0.f;
#pragma unroll
    for (int i = 0; i < CPS; i++) {
        float nr = sr * ar - si * ai, ni = sr * ai + si * ar;
        sr = nr; si = ni;
    }
    g_lamS_re[h] = sr; g_lamS_im[h] = si;
}

// ---------------- operand conversion ----------------
__global__ void convert_x_kernel(const float* __restrict__ x) {
    size_t i = (size_t)(blockIdx.x * blockDim.x + threadIdx.x) * 4;
    float4 v = *(const float4*)(x + i);
    *(__half2*)(g_xh + i)     = __floats2half2_rn(v.x, v.y);
    *(__half2*)(g_xh + i + 2) = __floats2half2_rn(v.z, v.w);
}

__global__ void convert_params_kernel(const float* __restrict__ B_re,
                                      const float* __restrict__ B_im,
                                      const float* __restrict__ C_re,
                                      const float* __restrict__ C_im) {
    int i = blockIdx.x * blockDim.x + threadIdx.x;
    g_Bh[0][i] = __float2half(B_re[i]);
    g_Bh[1][i] = __float2half(B_im[i]);
    g_Ch[0][i] = __float2half(C_re[i]);
    g_Ch[1][i] = __float2half(-C_im[i]);
}

// ---------------- asm helpers ----------------
__device__ __forceinline__ uint32_t smem_u32(const void* p) {
    uint32_t a;
    asm("{ .reg .u64 t; cvta.to.shared.u64 t, %1; cvt.u32.u64 %0, t; }" : "=r"(a) : "l"(p));
    return a;
}
__device__ __forceinline__ void cp16(uint32_t dst, const void* src) {
    asm volatile("cp.async.cg.shared.global [%0], [%1], 16;" :: "r"(dst), "l"(src));
}
#define CP_COMMIT() asm volatile("cp.async.commit_group;" ::: "memory")
#define CP_WAIT3()  asm volatile("cp.async.wait_group 3;" ::: "memory")
#define LDM_X4(r, a)                                                     \
    asm volatile("ldmatrix.sync.aligned.m8n8.x4.shared.b16 {%0,%1,%2,%3}, [%4];" \
        : "=r"((r)[0]), "=r"((r)[1]), "=r"((r)[2]), "=r"((r)[3]) : "r"(a))

__device__ __forceinline__ void mma_f16(float& c0, float& c1, float& c2, float& c3,
                                        uint32_t a0, uint32_t a1, uint32_t a2, uint32_t a3,
                                        uint32_t b0, uint32_t b1) {
    asm volatile(
        "mma.sync.aligned.m16n8k16.row.col.f32.f16.f16.f32 "
        "{%0,%1,%2,%3}, {%4,%5,%6,%7}, {%8,%9}, {%0,%1,%2,%3};"
        : "+f"(c0), "+f"(c1), "+f"(c2), "+f"(c3)
        : "r"(a0), "r"(a1), "r"(a2), "r"(a3), "r"(b0), "r"(b1));
}

// ---------------- pipelined fp16 GEMM, tile 128x128 (R14-proven shape) ----------------
// mode 0: Bu planes. A = g_xh; B = g_Bh[z]. K=512. epi *gam -> half Bu planes.
// mode 2: outputs.   A = xsh_re|xsh_im; B = Ch0|Ch1. K=1024. epi + xh*D (fp32 out).
// 8 warps (2m x 4n), warp tile 64x32, BK=32, 5-stage cp.async, ldmatrix, 2 CTAs/SM.
__global__ __launch_bounds__(256, 2) void gemm_f16p_kernel(
    const float* __restrict__ Dvec, float* __restrict__ Cout_ext, int mode)
{
    extern __shared__ __align__(16) char dsm[];
    const uint32_t smb = smem_u32(dsm);

    const int t    = threadIdx.x;
    const int lane = t & 31;
    const int wid  = t >> 5;
    const int wm0  = (wid >> 2) * 64;
    const int wn0  = (wid & 3) * 32;
    const int m0   = blockIdx.y * 128;
    const int n0   = blockIdx.x * 128;

    int KT = (mode == 0) ? DM / BKH : 2 * DH / BKH;

    float acc[4][4][4];
#pragma unroll
    for (int a = 0; a < 4; a++)
#pragma unroll
        for (int b = 0; b < 4; b++)
#pragma unroll
            for (int c = 0; c < 4; c++) acc[a][b][c] = 0.f;

    int cl[2], cs[2], cr[2], ck[2];
#pragma unroll
    for (int i = 0; i < 2; i++) {
        int g = t + i * 256;
        cl[i] = g >> 3;
        cs[i] = g & 7;
        cr[i] = (cl[i] << 1) + (cs[i] >> 2);
        ck[i] = (cs[i] & 3) * 8;
    }

#define ISSUE(s) do {                                                         \
        int kg = (s) * BKH;                                                   \
        const __half* Ap_; const __half* Bp_; int kb_;                        \
        if (mode == 0) { Ap_ = g_xh; Bp_ = g_Bh[blockIdx.z]; kb_ = kg; }      \
        else if (kg < DH) { Ap_ = g_xsh_re; Bp_ = g_Ch[0]; kb_ = kg; }        \
        else              { Ap_ = g_xsh_im; Bp_ = g_Ch[1]; kb_ = kg - DH; }   \
        uint32_t st_ = smb + ((s) % STAGES) * STAGE_BYTES;                    \
        _Pragma("unroll")                                                     \
        for (int i = 0; i < 2; i++) {                                         \
            uint32_t off = cl[i] * 128 + ((cs[i] ^ (cl[i] & 7)) << 4);        \
            cp16(st_ + off,        Ap_ + (size_t)(m0 + cr[i]) * DM + kb_ + ck[i]); \
            cp16(st_ + 8192 + off, Bp_ + (size_t)(n0 + cr[i]) * DM + kb_ + ck[i]); \
        }                                                                     \
    } while (0)

#pragma unroll
    for (int s = 0; s < STAGES - 1; s++) { ISSUE(s); CP_COMMIT(); }

    for (int kt = 0; kt < KT; kt++) {
        CP_WAIT3();
        __syncthreads();
        if (kt + STAGES - 1 < KT) ISSUE(kt + STAGES - 1);
        CP_COMMIT();

        uint32_t Ast = smb + (kt % STAGES) * STAGE_BYTES;
        uint32_t Bst = Ast + 8192;

#pragma unroll
        for (int j = 0; j < 2; j++) {
            uint32_t af[4][4];
#pragma unroll
            for (int mt = 0; mt < 4; mt++) {
                int r  = wm0 + mt * 16 + (lane & 7) + ((lane >> 3) & 1) * 8;
                int kc = 2 * j + (lane >> 4);
                int line = r >> 1, sub = ((r & 1) << 2) | kc;
                LDM_X4(af[mt], Ast + line * 128 + ((sub ^ (line & 7)) << 4));
            }
            uint32_t bq[2][4];
#pragma unroll
            for (int np = 0; np < 2; np++) {
                int n  = wn0 + np * 16 + (lane & 7) + ((lane >> 4) ? 8 : 0);
                int kc = 2 * j + ((lane >> 3) & 1);
                int line = n >> 1, sub = ((n & 1) << 2) | kc;
                LDM_X4(bq[np], Bst + line * 128 + ((sub ^ (line & 7)) << 4));
            }
#pragma unroll
            for (int mt = 0; mt < 4; mt++)
#pragma unroll
                for (int nt = 0; nt < 4; nt++)
                    mma_f16(acc[mt][nt][0], acc[mt][nt][1], acc[mt][nt][2], acc[mt][nt][3],
                            af[mt][0], af[mt][1], af[mt][2], af[mt][3],
                            bq[nt >> 1][(nt & 1) * 2], bq[nt >> 1][(nt & 1) * 2 + 1]);
        }
    }

    // ---- epilogue ----
#pragma unroll
    for (int mt = 0; mt < 4; mt++) {
        int row0 = m0 + wm0 + mt * 16 + (lane >> 2);
#pragma unroll
        for (int nt = 0; nt < 4; nt++) {
            int col0 = n0 + wn0 + nt * 8 + (lane & 3) * 2;
            float v0 = acc[mt][nt][0], v1 = acc[mt][nt][1];
            float v2 = acc[mt][nt][2], v3 = acc[mt][nt][3];
            if (mode == 0) {
                __half* base = blockIdx.z ? g_Buh_im : g_Buh_re;
                float gx = g_gam[col0], gy = g_gam[col0 + 1];
                *(__half2*)&base[(size_t)row0 * DH + col0] =
                    __floats2half2_rn(v0 * gx, v1 * gy);
                *(__half2*)&base[(size_t)(row0 + 8) * DH + col0] =
                    __floats2half2_rn(v2 * gx, v3 * gy);
            } else {
                float2 dv = *(const float2*)&Dvec[col0];
                float2 x0 = __half22float2(*(const __half2*)&g_xh[(size_t)row0 * DM + col0]);
                float2 x1 = __half22float2(*(const __half2*)&g_xh[(size_t)(row0 + 8) * DM + col0]);
                *(float2*)&Cout_ext[(size_t)row0 * DM + col0] =
                    make_float2(v0 + x0.x * dv.x, v1 + x0.y * dv.y);
                *(float2*)&Cout_ext[(size_t)(row0 + 8) * DM + col0] =
                    make_float2(v2 + x1.x * dv.x, v3 + x1.y * dv.y);
            }
        }
    }
}

// ---------------- scan passes (2 h per thread, half2/float2) ----------------
__global__ void chunk_reduce_kernel() {
    int c = blockIdx.x, h2 = threadIdx.x;          // 256 threads, h = 2*h2
    int h = h2 * 2;
    float2 lr = *(const float2*)&g_lam_re[h];
    float2 li = *(const float2*)&g_lam_im[h];
    float sr0 = 0.f, si0 = 0.f, sr1 = 0.f, si1 = 0.f;
    int any = 0, base = c * LCH;
#pragma unroll 4
    for (int t = 0; t < LCH; t++) {
        int s = g_start[base + t];
        any |= s;
        float2 br = __half22float2(*(const __half2*)&g_Buh_re[(size_t)(base + t) * DH + h]);
        float2 bi = __half22float2(*(const __half2*)&g_Buh_im[(size_t)(base + t) * DH + h]);
        if (s) { sr0 = br.x; si0 = bi.x; sr1 = br.y; si1 = bi.y; }
        else {
            float n0 = lr.x * sr0 - li.x * si0 + br.x;
            float m0 = lr.x * si0 + li.x * sr0 + bi.x;
            float n1 = lr.y * sr1 - li.y * si1 + br.y;
            float m1 = lr.y * si1 + li.y * sr1 + bi.y;
            sr0 = n0; si0 = m0; sr1 = n1; si1 = m1;
        }
    }
    *(float2*)&g_cb_re[c * DH + h] = make_float2(sr0, sr1);
    *(float2*)&g_cb_im[c * DH + h] = make_float2(si0, si1);
    if (h2 == 0) g_anystart[c] = any;
}

__global__ void super_reduce_kernel() {
    int s = blockIdx.x, h = threadIdx.x;
    float Lr = g_lamL_re[h], Li = g_lamL_im[h];
    float sr = 0.f, si = 0.f;
    int anyS = 0, base = s * CPS;
#pragma unroll 4
    for (int j = 0; j < CPS; j++) {
        int c = base + j, a = g_anystart[c];
        anyS |= a;
        float br = g_cb_re[c * DH + h], bi = g_cb_im[c * DH + h];
        if (a) { sr = br; si = bi; }
        else {
            float nr = Lr * sr - Li * si + br, ni = Lr * si + Li * sr + bi;
            sr = nr; si = ni;
        }
    }
    g_sb_re[s * DH + h] = sr; g_sb_im[s * DH + h] = si;
    if (h == 0) g_sany[s] = anyS;
}

__global__ void super_scan_kernel(const float* __restrict__ state) {
    int h = threadIdx.x;
    float sr = state[h], si = 0.f;
    float Sr = g_lamS_re[h], Si = g_lamS_im[h];
#pragma unroll 4
    for (int s = 0; s < NSUP; s++) {
        g_sinit_re[s * DH + h] = sr; g_sinit_im[s * DH + h] = si;
        float br = g_sb_re[s * DH + h], bi = g_sb_im[s * DH + h];
        if (g_sany[s]) { sr = br; si = bi; }
        else {
            float nr = Sr * sr - Si * si + br, ni = Sr * si + Si * sr + bi;
            sr = nr; si = ni;
        }
    }
}

__global__ void super_expand_kernel() {
    int s = blockIdx.x, h = threadIdx.x;
    float Lr = g_lamL_re[h], Li = g_lamL_im[h];
    float sr = g_sinit_re[s * DH + h], si = g_sinit_im[s * DH + h];
    int base = s * CPS;
#pragma unroll 4
    for (int j = 0; j < CPS; j++) {
        int c = base + j;
        g_init_re[c * DH + h] = sr; g_init_im[c * DH + h] = si;
        float br = g_cb_re[c * DH + h], bi = g_cb_im[c * DH + h];
        if (g_anystart[c]) { sr = br; si = bi; }
        else {
            float nr = Lr * sr - Li * si + br, ni = Lr * si + Li * sr + bi;
            sr = nr; si = ni;
        }
    }
}

// expand: fp16 xs planes for GEMM2 + fp32 final-state capture (2 h / thread)
__global__ void chunk_expand_kernel() {
    int c = blockIdx.x, h2 = threadIdx.x;
    int h = h2 * 2;
    float2 lr = *(const float2*)&g_lam_re[h];
    float2 li = *(const float2*)&g_lam_im[h];
    float2 ir = *(const float2*)&g_init_re[c * DH + h];
    float2 ii = *(const float2*)&g_init_im[c * DH + h];
    float sr0 = ir.x, si0 = ii.x, sr1 = ir.y, si1 = ii.y;
    int base = c * LCH;
#pragma unroll 4
    for (int t = 0; t < LCH; t++) {
        float2 br = __half22float2(*(const __half2*)&g_Buh_re[(size_t)(base + t) * DH + h]);
        float2 bi = __half22float2(*(const __half2*)&g_Buh_im[(size_t)(base + t) * DH + h]);
        if (g_start[base + t]) { sr0 = br.x; si0 = bi.x; sr1 = br.y; si1 = bi.y; }
        else {
            float n0 = lr.x * sr0 - li.x * si0 + br.x;
            float m0 = lr.x * si0 + li.x * sr0 + bi.x;
            float n1 = lr.y * sr1 - li.y * si1 + br.y;
            float m1 = lr.y * si1 + li.y * sr1 + bi.y;
            sr0 = n0; si0 = m0; sr1 = n1; si1 = m1;
        }
        *(__half2*)&g_xsh_re[(size_t)(base + t) * DH + h] = __floats2half2_rn(sr0, sr1);
        *(__half2*)&g_xsh_im[(size_t)(base + t) * DH + h] = __floats2half2_rn(si0, si1);
    }
    if (c == NCH - 1) {
        *(float2*)&g_fin_re[h] = make_float2(sr0, sr1);
        *(float2*)&g_fin_im[h] = make_float2(si0, si1);
    }
}

__global__ void write_state_kernel(float* __restrict__ out, int mode) {
    int h = threadIdx.x;
    if (mode == 0) { out[h] = g_fin_re[h]; out[DH + h] = g_fin_im[h]; }
    else           { out[h] = g_fin_re[h]; }
}

// ---------------- launch ----------------
extern "C" void kernel_launch(void* const* d_in, const int* in_sizes, int n_in,
                              void* d_out, int out_size) {
    const float*        state     = (const float*)d_in[0];
    const float*        x         = (const float*)d_in[1];
    const unsigned int* start_raw = (const unsigned int*)d_in[2];
    const float*        theta_log = (const float*)d_in[3];
    const float*        nu_log    = (const float*)d_in[4];
    const float*        gamma_log = (const float*)d_in[5];
    const float*        B_re      = (const float*)d_in[6];
    const float*        B_im      = (const float*)d_in[7];
    const float*        C_re      = (const float*)d_in[8];
    const float*        C_im      = (const float*)d_in[9];
    const float*        Dvec      = (const float*)d_in[10];

    const long long full = (long long)T_LEN * DM;
    int state_elems = (int)((long long)out_size - full);
    int mode; int out_off;
    if (state_elems >= 2 * DH) { mode = 0; out_off = 2 * DH; }
    else                       { mode = 1; out_off = DH; }

    float* out = (float*)d_out;
    float* outputs = out + out_off;

    static int smem_set = 0;
    if (!smem_set) {
        cudaFuncSetAttribute(gemm_f16p_kernel,
                             cudaFuncAttributeMaxDynamicSharedMemorySize, SMEM_DYN);
        smem_set = 1;
    }

    start_convert_kernel<<<1, 256>>>(start_raw);
    prep_kernel<<<1, DH>>>(theta_log, nu_log, gamma_log);
    convert_x_kernel<<<(T_LEN * DM / 4) / 256, 256>>>(x);
    convert_params_kernel<<<(DH * DM) / 256, 256>>>(B_re, B_im, C_re, C_im);

    dim3 g1(DH / 128, T_LEN / 128, 2);
    gemm_f16p_kernel<<<g1, 256, SMEM_DYN>>>(Dvec, nullptr, 0);

    chunk_reduce_kernel<<<NCH, 256>>>();
    super_reduce_kernel<<<NSUP, DH>>>();
    super_scan_kernel<<<1, DH>>>(state);
    super_expand_kernel<<<NSUP, DH>>>();
    chunk_expand_kernel<<<NCH, 256>>>();

    dim3 g2(DM / 128, T_LEN / 128, 1);
    gemm_f16p_kernel<<<g2, 256, SMEM_DYN>>>(Dvec, outputs, 2);

    write_state_kernel<<<1, DH>>>(out, mode);
}